// round 13
// baseline (speedup 1.0000x reference)
#include <cuda_runtime.h>
#include <cuda_bf16.h>
#include <math.h>
#include <stdint.h>

// Problem constants
#define BB 2
#define SS 4096
#define DD 2048
#define MM (BB * SS)          // 8192 GEMM rows
#define MN ((size_t)MM * DD)  // elements per tensor
#define CH 64                 // scan chunks
#define CL (SS / CH)          // steps per chunk

#define Bb_M 128
#define Bb_N 128
#define Bb_K 64
#define KITERS 96             // 3 * 2048 / 64  (bf16x3 split folded into K)
#define NSTAGE 3
#define STAGE_BYTES 32768     // 16KB A + 16KB B

// ---------------- scratch (static device memory) ---------------------------
__device__ __align__(256) __nv_bfloat16 g_gA_hi[MN];
__device__ __align__(256) __nv_bfloat16 g_gA_lo[MN];
__device__ __align__(256) __nv_bfloat16 g_WaT_hi[(size_t)DD * DD];
__device__ __align__(256) __nv_bfloat16 g_WaT_lo[(size_t)DD * DD];
__device__ __align__(256) __nv_bfloat16 g_WbT_hi[(size_t)DD * DD];
__device__ __align__(256) __nv_bfloat16 g_WbT_lo[(size_t)DD * DD];
__device__ __align__(256) float g_alpha[MN];  // sigmoid gate
__device__ __align__(256) float g_beta[MN];   // silu gate
__device__ __align__(256) float g_Ac[BB * CH * DD];
__device__ __align__(256) float g_Xc[BB * CH * DD];
__device__ __align__(256) float g_Hin[BB * CH * DD];

// ---------------- PTX helpers ----------------------------------------------
static __device__ __forceinline__ uint32_t smem_u32(const void* p) {
  uint32_t a;
  asm("{ .reg .u64 t; cvta.to.shared.u64 t, %1; cvt.u32.u64 %0, t; }"
      : "=r"(a) : "l"(p));
  return a;
}

static __device__ __forceinline__ void cpa16(uint32_t dst, const void* src) {
  asm volatile("cp.async.cg.shared.global [%0], [%1], 16;" :: "r"(dst), "l"(src));
}
#define CPA_COMMIT() asm volatile("cp.async.commit_group;" ::: "memory")
#define CPA_WAIT1() asm volatile("cp.async.wait_group 1;" ::: "memory")

static __device__ __forceinline__ void ldmx4(uint32_t* r, uint32_t addr) {
  asm volatile(
      "ldmatrix.sync.aligned.m8n8.x4.shared.b16 {%0, %1, %2, %3}, [%4];"
      : "=r"(r[0]), "=r"(r[1]), "=r"(r[2]), "=r"(r[3]) : "r"(addr));
}

static __device__ __forceinline__ void mma16816(
    float* d, const uint32_t* a, uint32_t b0, uint32_t b1) {
  asm volatile(
      "mma.sync.aligned.m16n8k16.row.col.f32.bf16.bf16.f32 "
      "{%0, %1, %2, %3}, {%4, %5, %6, %7}, {%8, %9}, {%0, %1, %2, %3};"
      : "+f"(d[0]), "+f"(d[1]), "+f"(d[2]), "+f"(d[3])
      : "r"(a[0]), "r"(a[1]), "r"(a[2]), "r"(a[3]), "r"(b0), "r"(b1));
}

static __device__ __forceinline__ float fast_sqrt(float z) {
  float r;
  asm("sqrt.approx.f32 %0, %1;" : "=f"(r) : "f"(z));
  return r;
}

// ---------------- K0: gate = rms(c)+rms(prev), split to bf16 hi/lo ----------
static __device__ __forceinline__ void split2(float a, float b,
                                              __nv_bfloat162& h, __nv_bfloat162& l) {
  __nv_bfloat16 ha = __float2bfloat16(a), hb = __float2bfloat16(b);
  h = __halves2bfloat162(ha, hb);
  l = __halves2bfloat162(__float2bfloat16(a - __bfloat162float(ha)),
                         __float2bfloat16(b - __bfloat162float(hb)));
}

__global__ __launch_bounds__(256) void k_rmsnorm_split(
    const float* __restrict__ c, const float* __restrict__ p) {
  const int row = blockIdx.x;
  const int tid = threadIdx.x;
  const float4* c4 = (const float4*)(c + (size_t)row * DD);
  const float4* p4 = (const float4*)(p + (size_t)row * DD);

  float4 cv0 = c4[tid], cv1 = c4[tid + 256];
  float4 pv0 = p4[tid], pv1 = p4[tid + 256];

  float sc = cv0.x * cv0.x + cv0.y * cv0.y + cv0.z * cv0.z + cv0.w * cv0.w +
             cv1.x * cv1.x + cv1.y * cv1.y + cv1.z * cv1.z + cv1.w * cv1.w;
  float sp = pv0.x * pv0.x + pv0.y * pv0.y + pv0.z * pv0.z + pv0.w * pv0.w +
             pv1.x * pv1.x + pv1.y * pv1.y + pv1.z * pv1.z + pv1.w * pv1.w;
#pragma unroll
  for (int off = 16; off > 0; off >>= 1) {
    sc += __shfl_xor_sync(0xffffffffu, sc, off);
    sp += __shfl_xor_sync(0xffffffffu, sp, off);
  }
  __shared__ float ssc[8], ssp[8];
  if ((tid & 31) == 0) { ssc[tid >> 5] = sc; ssp[tid >> 5] = sp; }
  __syncthreads();
  float tc = 0.f, tp = 0.f;
#pragma unroll
  for (int i = 0; i < 8; i++) { tc += ssc[i]; tp += ssp[i]; }
  const float rc = rsqrtf(tc * (1.0f / DD) + 1e-6f);
  const float rp = rsqrtf(tp * (1.0f / DD) + 1e-6f);

  float o[8];
  o[0] = cv0.x * rc + pv0.x * rp; o[1] = cv0.y * rc + pv0.y * rp;
  o[2] = cv0.z * rc + pv0.z * rp; o[3] = cv0.w * rc + pv0.w * rp;
  o[4] = cv1.x * rc + pv1.x * rp; o[5] = cv1.y * rc + pv1.y * rp;
  o[6] = cv1.z * rc + pv1.z * rp; o[7] = cv1.w * rc + pv1.w * rp;

  __nv_bfloat162* h2 = (__nv_bfloat162*)(g_gA_hi + (size_t)row * DD);
  __nv_bfloat162* l2 = (__nv_bfloat162*)(g_gA_lo + (size_t)row * DD);
  __nv_bfloat162 h, l;
  split2(o[0], o[1], h, l); h2[2 * tid + 0] = h; l2[2 * tid + 0] = l;
  split2(o[2], o[3], h, l); h2[2 * tid + 1] = h; l2[2 * tid + 1] = l;
  split2(o[4], o[5], h, l); h2[2 * (tid + 256) + 0] = h; l2[2 * (tid + 256) + 0] = l;
  split2(o[6], o[7], h, l); h2[2 * (tid + 256) + 1] = h; l2[2 * (tid + 256) + 1] = l;
}

// ---------------- K_w: transpose + bf16 split of W --------------------------
__global__ __launch_bounds__(256) void k_cvt_w(
    const float* __restrict__ Wa, const float* __restrict__ Wb) {
  __shared__ float t[32][33];
  const int mat = blockIdx.z;
  const float* __restrict__ W = mat ? Wb : Wa;
  __nv_bfloat16* __restrict__ Th = mat ? g_WbT_hi : g_WaT_hi;
  __nv_bfloat16* __restrict__ Tl = mat ? g_WbT_lo : g_WaT_lo;
  const int bx = blockIdx.x * 32;  // n base
  const int by = blockIdx.y * 32;  // k base
  const int x = threadIdx.x & 31, y0 = threadIdx.x >> 5;
#pragma unroll
  for (int i = 0; i < 4; i++) {
    int y = y0 + i * 8;
    t[y][x] = W[(size_t)(by + y) * DD + bx + x];  // W[k][n]
  }
  __syncthreads();
#pragma unroll
  for (int i = 0; i < 4; i++) {
    int y = y0 + i * 8;
    float v = t[x][y];  // WT[n=bx+y][k=by+x]
    __nv_bfloat16 h = __float2bfloat16(v);
    size_t idx = (size_t)(bx + y) * DD + by + x;
    Th[idx] = h;
    Tl[idx] = __float2bfloat16(v - __bfloat162float(h));
  }
}

// ---------------- K1: mma.sync dual GEMM, bf16x3, 8 warps, K=64 stages ------
// grid.x: 0..15 -> W_alpha/sigmoid N-tiles, 16..31 -> W_beta/silu N-tiles
// grid.y: 64 M-tiles. 128x128x64 CTA tile, 8 warps each 32x64, 2 CTAs/SM.
__global__ __launch_bounds__(256, 2) void k_gemm_mma(
    const float* __restrict__ ba, const float* __restrict__ bb) {
  extern __shared__ __align__(1024) char sm[];  // NSTAGE * STAGE_BYTES
  const uint32_t smb = smem_u32(sm);

  const int tid = threadIdx.x;
  const int wid = tid >> 5, lid = tid & 31;
  const int bxv = blockIdx.x;
  const bool isBeta = (bxv >= 16);
  const int n0 = (isBeta ? bxv - 16 : bxv) * Bb_N;
  const int m0 = blockIdx.y * Bb_M;
  const __nv_bfloat16* __restrict__ Bhi = isBeta ? g_WbT_hi : g_WaT_hi;
  const __nv_bfloat16* __restrict__ Blo = isBeta ? g_WbT_lo : g_WaT_lo;
  const float* __restrict__ bias = isBeta ? bb : ba;

  // each stage: A 1024 x 16B chunks + B 1024 x 16B chunks; 256 thr -> 4 each
  auto load_stage = [&](int kc, int buf) {
    const int seg = kc >> 5;            // 32 k-chunks per segment
    const int kk = (kc & 31) * Bb_K;
    const __nv_bfloat16* __restrict__ As =
        ((seg == 1) ? g_gA_lo : g_gA_hi) + (size_t)m0 * DD + kk;
    const __nv_bfloat16* __restrict__ Bs =
        ((seg == 2) ? Blo : Bhi) + (size_t)n0 * DD + kk;
    const uint32_t ab = smb + buf * STAGE_BYTES;
    const uint32_t bbuf = ab + 16384;
#pragma unroll
    for (int i = 0; i < 4; i++) {
      int id = tid + i * 256;           // 0..1023
      int row = id >> 3, cc = id & 7;
      uint32_t soff = (uint32_t)(row * 128 + ((cc ^ (row & 7)) << 4));
      size_t goff = (size_t)row * DD + cc * 8;
      cpa16(ab + soff, As + goff);
      cpa16(bbuf + soff, Bs + goff);
    }
  };

  // warp tiling: wm in {0..3} (32 rows), wn in {0,1} (64 cols)
  const int wm = wid & 3, wn = wid >> 2;
  const int lr = lid & 15, c8 = lid >> 4;

  // Fragment offsets. Note bits 4-6 of (stage_base + row*128) are zero, so
  // base + (x<<4) == base ^ (x<<4) for x<8; fold (swz ^ c8) into one XOR mask.
  uint32_t a_msk[2];
#pragma unroll
  for (int mt = 0; mt < 2; mt++) {
    int row = wm * 32 + mt * 16 + lr;
    a_msk[mt] = (uint32_t)(row * 128) ^ (uint32_t)(((row & 7) ^ c8) << 4);
  }
  uint32_t b_msk[4];
#pragma unroll
  for (int bt = 0; bt < 4; bt++) {
    int row = wn * 64 + bt * 16 + lr;
    b_msk[bt] = (uint32_t)(row * 128) ^ (uint32_t)(((row & 7) ^ c8) << 4);
  }

  float ac[2][8][4];
#pragma unroll
  for (int i = 0; i < 2; i++)
#pragma unroll
    for (int j = 0; j < 8; j++)
#pragma unroll
      for (int q = 0; q < 4; q++) ac[i][j][q] = 0.f;

  // prefetch first NSTAGE-1 stages
#pragma unroll
  for (int s = 0; s < NSTAGE - 1; s++) { load_stage(s, s); CPA_COMMIT(); }

  int cmp_buf = 0, ld_buf = NSTAGE - 1;
#pragma unroll 1
  for (int kc = 0; kc < KITERS; kc++) {
    CPA_WAIT1();
    __syncthreads();

    const uint32_t abase = smb + cmp_buf * STAGE_BYTES;
    const uint32_t bbase = abase + 16384;

    // per-fragment base addresses for this buffer (single ADD each)
    uint32_t aP[2], bP[4];
#pragma unroll
    for (int mt = 0; mt < 2; mt++) aP[mt] = abase + a_msk[mt];
#pragma unroll
    for (int bt = 0; bt < 4; bt++) bP[bt] = bbase + b_msk[bt];

#pragma unroll
    for (int ks = 0; ks < 4; ks++) {
      const uint32_t kx = (uint32_t)(ks << 5);  // (ks*2)<<4, literal per ks
      uint32_t af[2][4], bfr[4][4];
#pragma unroll
      for (int mt = 0; mt < 2; mt++) ldmx4(af[mt], aP[mt] ^ kx);
#pragma unroll
      for (int bt = 0; bt < 4; bt++) ldmx4(bfr[bt], bP[bt] ^ kx);
#pragma unroll
      for (int mt = 0; mt < 2; mt++) {
#pragma unroll
        for (int nt = 0; nt < 8; nt++) {
          const int bt = nt >> 1, sel = nt & 1;
          mma16816(ac[mt][nt], af[mt], bfr[bt][sel], bfr[bt][2 + sel]);
        }
      }
      // overlap: issue next-stage loads after the first ks block
      if (ks == 0) {
        if (kc + NSTAGE - 1 < KITERS) load_stage(kc + NSTAGE - 1, ld_buf);
        CPA_COMMIT();
      }
    }

    cmp_buf = (cmp_buf + 1 == NSTAGE) ? 0 : cmp_buf + 1;
    ld_buf = (ld_buf + 1 == NSTAGE) ? 0 : ld_buf + 1;
  }

  // epilogue: bias + sigmoid/silu, direct global store
  float* __restrict__ dst = isBeta ? g_beta : g_alpha;
  const int g = lid >> 2, tig = lid & 3;
  float bi0[8], bi1[8];
#pragma unroll
  for (int nt = 0; nt < 8; nt++) {
    int col = n0 + wn * 64 + nt * 8 + tig * 2;
    bi0[nt] = __ldg(bias + col);
    bi1[nt] = __ldg(bias + col + 1);
  }
#pragma unroll
  for (int mt = 0; mt < 2; mt++) {
    const int row = m0 + wm * 32 + mt * 16 + g;
#pragma unroll
    for (int nt = 0; nt < 8; nt++) {
      const int col = n0 + wn * 64 + nt * 8 + tig * 2;
      float pr, sg;
      float2 v0, v1;
      pr = ac[mt][nt][0] + bi0[nt];
      sg = 1.0f / (1.0f + __expf(-pr)); v0.x = isBeta ? pr * sg : sg;
      pr = ac[mt][nt][1] + bi1[nt];
      sg = 1.0f / (1.0f + __expf(-pr)); v0.y = isBeta ? pr * sg : sg;
      pr = ac[mt][nt][2] + bi0[nt];
      sg = 1.0f / (1.0f + __expf(-pr)); v1.x = isBeta ? pr * sg : sg;
      pr = ac[mt][nt][3] + bi1[nt];
      sg = 1.0f / (1.0f + __expf(-pr)); v1.y = isBeta ? pr * sg : sg;
      *(float2*)(dst + (size_t)row * DD + col) = v0;
      *(float2*)(dst + (size_t)(row + 8) * DD + col) = v1;
    }
  }
}

// ---------------- x helper ---------------------------------------------------
static __device__ __forceinline__ float x_of(float a, float be, float vv) {
  return vv * be * fast_sqrt(fmaxf(1.0f - a * a, 1e-6f));
}

// ---------------- K3a: per-chunk (A_prod, X_scan), x fused -------------------
__global__ __launch_bounds__(256) void k_scan_chunks(const float* __restrict__ v) {
  const int d = blockIdx.x * 256 + threadIdx.x;
  const int ch = blockIdx.y;
  const int b = blockIdx.z;
  size_t base = ((size_t)(b * SS + ch * CL)) * DD + d;
  float A = 1.f, X = 0.f;
#pragma unroll 8
  for (int t = 0; t < CL; t++) {
    size_t idx = base + (size_t)t * DD;
    float a = g_alpha[idx];
    float x = x_of(a, g_beta[idx], v[idx]);
    X = fmaf(a, X, x);
    A *= a;
  }
  const int o = (b * CH + ch) * DD + d;
  g_Ac[o] = A;
  g_Xc[o] = X;
}

// ---------------- K3b: carry scan across chunks ------------------------------
__global__ __launch_bounds__(256) void k_scan_carry() {
  const int g = blockIdx.x * 256 + threadIdx.x;
  const int b = g / DD;
  const int d = g % DD;
  float H = 0.f;
#pragma unroll 8
  for (int c = 0; c < CH; c++) {
    const int idx = (b * CH + c) * DD + d;
    g_Hin[idx] = H;
    H = fmaf(g_Ac[idx], H, g_Xc[idx]);
  }
}

// ---------------- K3c: final rescan + outputs, x fused -----------------------
__global__ __launch_bounds__(256) void k_scan_final(
    const float* __restrict__ v, const float* __restrict__ outp,
    const float* __restrict__ cin, const float* __restrict__ gout,
    const float* __restrict__ gv, float* __restrict__ o_v,
    float* __restrict__ o_out, float* __restrict__ o_c,
    float* __restrict__ o_f) {
  const int d = blockIdx.x * 256 + threadIdx.x;
  const int ch = blockIdx.y;
  const int b = blockIdx.z;
  size_t base = ((size_t)(b * SS + ch * CL)) * DD + d;
  float h = g_Hin[(b * CH + ch) * DD + d];
  const float go = __ldg(&gout[d]);
  const float gvv = __ldg(&gv[d]);
#pragma unroll 8
  for (int t = 0; t < CL; t++) {
    size_t idx = base + (size_t)t * DD;
    float a = g_alpha[idx];
    float vv = v[idx];
    float x = x_of(a, g_beta[idx], vv);
    h = fmaf(a, h, x);
    o_f[idx] = h;
    o_v[idx] = fmaf(h, gvv, vv);
    o_out[idx] = fmaf(h, go, outp[idx]);
    o_c[idx] = cin[idx];
  }
}

// ---------------- launch -----------------------------------------------------
extern "C" void kernel_launch(void* const* d_in, const int* in_sizes, int n_in,
                              void* d_out, int out_size) {
  const float* v = (const float*)d_in[0];
  const float* out = (const float*)d_in[1];
  const float* c = (const float*)d_in[2];
  const float* prev = (const float*)d_in[3];
  const float* Wa = (const float*)d_in[4];
  const float* ba = (const float*)d_in[5];
  const float* Wb = (const float*)d_in[6];
  const float* bb = (const float*)d_in[7];
  const float* gout = (const float*)d_in[8];
  const float* gv = (const float*)d_in[9];

  float* o_v = (float*)d_out;
  float* o_out = o_v + MN;
  float* o_c = o_out + MN;
  float* o_f = o_c + MN;

  // K0 + W conversion (independent)
  k_rmsnorm_split<<<MM, 256>>>(c, prev);
  {
    dim3 wgrid(DD / 32, DD / 32, 2);
    k_cvt_w<<<wgrid, 256>>>(Wa, Wb);
  }

  // K1: dual GEMM via mma.sync (bf16x3), 8 warps, K=64, 3-stage pipeline
  {
    const int SMEM_BYTES = NSTAGE * STAGE_BYTES;  // 96 KB
    cudaFuncSetAttribute(k_gemm_mma, cudaFuncAttributeMaxDynamicSharedMemorySize,
                         SMEM_BYTES);
    dim3 ggrid(32, 64);
    k_gemm_mma<<<ggrid, 256, SMEM_BYTES>>>(ba, bb);
  }

  // K3: chunked scan (x fused)  [4th launch -> ncu profiles k_scan_chunks]
  dim3 agrid(DD / 256, CH, BB);
  k_scan_chunks<<<agrid, 256>>>(v);
  k_scan_carry<<<(BB * DD) / 256, 256>>>();
  k_scan_final<<<agrid, 256>>>(v, out, c, gout, gv, o_v, o_out, o_c, o_f);
}

// round 14
// speedup vs baseline: 1.0445x; 1.0445x over previous
#include <cuda_runtime.h>
#include <cuda_bf16.h>
#include <math.h>
#include <stdint.h>

// Problem constants
#define BB 2
#define SS 4096
#define DD 2048
#define MM (BB * SS)          // 8192 GEMM rows
#define MN ((size_t)MM * DD)  // elements per tensor
#define CH 64                 // scan chunks
#define CL (SS / CH)          // steps per chunk

#define Bb_M 128
#define Bb_N 128
#define Bb_K 64
#define KITERS 96             // 3 * 2048 / 64  (bf16x3 split folded into K)
#define NSTAGE 3
#define STAGE_BYTES 32768     // 16KB A + 16KB B

// ---------------- scratch (static device memory) ---------------------------
__device__ __align__(256) __nv_bfloat16 g_gA_hi[MN];
__device__ __align__(256) __nv_bfloat16 g_gA_lo[MN];
__device__ __align__(256) __nv_bfloat16 g_WaT_hi[(size_t)DD * DD];
__device__ __align__(256) __nv_bfloat16 g_WaT_lo[(size_t)DD * DD];
__device__ __align__(256) __nv_bfloat16 g_WbT_hi[(size_t)DD * DD];
__device__ __align__(256) __nv_bfloat16 g_WbT_lo[(size_t)DD * DD];
__device__ __align__(256) float g_alpha[MN];  // sigmoid gate
__device__ __align__(256) float g_beta[MN];   // silu gate
__device__ __align__(256) float g_Ac[BB * CH * DD];
__device__ __align__(256) float g_Xc[BB * CH * DD];
__device__ __align__(256) float g_Hin[BB * CH * DD];

// ---------------- PTX helpers ----------------------------------------------
static __device__ __forceinline__ uint32_t smem_u32(const void* p) {
  uint32_t a;
  asm("{ .reg .u64 t; cvta.to.shared.u64 t, %1; cvt.u32.u64 %0, t; }"
      : "=r"(a) : "l"(p));
  return a;
}

static __device__ __forceinline__ void cpa16(uint32_t dst, const void* src) {
  asm volatile("cp.async.cg.shared.global [%0], [%1], 16;" :: "r"(dst), "l"(src));
}
#define CPA_COMMIT() asm volatile("cp.async.commit_group;" ::: "memory")
#define CPA_WAIT1() asm volatile("cp.async.wait_group 1;" ::: "memory")

static __device__ __forceinline__ void ldmx4(uint32_t* r, uint32_t addr) {
  asm volatile(
      "ldmatrix.sync.aligned.m8n8.x4.shared.b16 {%0, %1, %2, %3}, [%4];"
      : "=r"(r[0]), "=r"(r[1]), "=r"(r[2]), "=r"(r[3]) : "r"(addr));
}

static __device__ __forceinline__ void mma16816(
    float* d, const uint32_t* a, uint32_t b0, uint32_t b1) {
  asm volatile(
      "mma.sync.aligned.m16n8k16.row.col.f32.bf16.bf16.f32 "
      "{%0, %1, %2, %3}, {%4, %5, %6, %7}, {%8, %9}, {%0, %1, %2, %3};"
      : "+f"(d[0]), "+f"(d[1]), "+f"(d[2]), "+f"(d[3])
      : "r"(a[0]), "r"(a[1]), "r"(a[2]), "r"(a[3]), "r"(b0), "r"(b1));
}

static __device__ __forceinline__ float fast_sqrt(float z) {
  float r;
  asm("sqrt.approx.f32 %0, %1;" : "=f"(r) : "f"(z));
  return r;
}

// ---------------- K0: gate = rms(c)+rms(prev), split to bf16 hi/lo ----------
// Also writes o_c = c (fused copy; c is already in registers here).
static __device__ __forceinline__ void split2(float a, float b,
                                              __nv_bfloat162& h, __nv_bfloat162& l) {
  __nv_bfloat16 ha = __float2bfloat16(a), hb = __float2bfloat16(b);
  h = __halves2bfloat162(ha, hb);
  l = __halves2bfloat162(__float2bfloat16(a - __bfloat162float(ha)),
                         __float2bfloat16(b - __bfloat162float(hb)));
}

__global__ __launch_bounds__(256) void k_rmsnorm_split(
    const float* __restrict__ c, const float* __restrict__ p,
    float* __restrict__ o_c) {
  const int row = blockIdx.x;
  const int tid = threadIdx.x;
  const float4* c4 = (const float4*)(c + (size_t)row * DD);
  const float4* p4 = (const float4*)(p + (size_t)row * DD);
  float4* oc4 = (float4*)(o_c + (size_t)row * DD);

  float4 cv0 = c4[tid], cv1 = c4[tid + 256];
  float4 pv0 = p4[tid], pv1 = p4[tid + 256];

  // fused o_c = c
  oc4[tid] = cv0;
  oc4[tid + 256] = cv1;

  float sc = cv0.x * cv0.x + cv0.y * cv0.y + cv0.z * cv0.z + cv0.w * cv0.w +
             cv1.x * cv1.x + cv1.y * cv1.y + cv1.z * cv1.z + cv1.w * cv1.w;
  float sp = pv0.x * pv0.x + pv0.y * pv0.y + pv0.z * pv0.z + pv0.w * pv0.w +
             pv1.x * pv1.x + pv1.y * pv1.y + pv1.z * pv1.z + pv1.w * pv1.w;
#pragma unroll
  for (int off = 16; off > 0; off >>= 1) {
    sc += __shfl_xor_sync(0xffffffffu, sc, off);
    sp += __shfl_xor_sync(0xffffffffu, sp, off);
  }
  __shared__ float ssc[8], ssp[8];
  if ((tid & 31) == 0) { ssc[tid >> 5] = sc; ssp[tid >> 5] = sp; }
  __syncthreads();
  float tc = 0.f, tp = 0.f;
#pragma unroll
  for (int i = 0; i < 8; i++) { tc += ssc[i]; tp += ssp[i]; }
  const float rc = rsqrtf(tc * (1.0f / DD) + 1e-6f);
  const float rp = rsqrtf(tp * (1.0f / DD) + 1e-6f);

  float o[8];
  o[0] = cv0.x * rc + pv0.x * rp; o[1] = cv0.y * rc + pv0.y * rp;
  o[2] = cv0.z * rc + pv0.z * rp; o[3] = cv0.w * rc + pv0.w * rp;
  o[4] = cv1.x * rc + pv1.x * rp; o[5] = cv1.y * rc + pv1.y * rp;
  o[6] = cv1.z * rc + pv1.z * rp; o[7] = cv1.w * rc + pv1.w * rp;

  __nv_bfloat162* h2 = (__nv_bfloat162*)(g_gA_hi + (size_t)row * DD);
  __nv_bfloat162* l2 = (__nv_bfloat162*)(g_gA_lo + (size_t)row * DD);
  __nv_bfloat162 h, l;
  split2(o[0], o[1], h, l); h2[2 * tid + 0] = h; l2[2 * tid + 0] = l;
  split2(o[2], o[3], h, l); h2[2 * tid + 1] = h; l2[2 * tid + 1] = l;
  split2(o[4], o[5], h, l); h2[2 * (tid + 256) + 0] = h; l2[2 * (tid + 256) + 0] = l;
  split2(o[6], o[7], h, l); h2[2 * (tid + 256) + 1] = h; l2[2 * (tid + 256) + 1] = l;
}

// ---------------- K_w: transpose + bf16 split of W --------------------------
__global__ __launch_bounds__(256) void k_cvt_w(
    const float* __restrict__ Wa, const float* __restrict__ Wb) {
  __shared__ float t[32][33];
  const int mat = blockIdx.z;
  const float* __restrict__ W = mat ? Wb : Wa;
  __nv_bfloat16* __restrict__ Th = mat ? g_WbT_hi : g_WaT_hi;
  __nv_bfloat16* __restrict__ Tl = mat ? g_WbT_lo : g_WaT_lo;
  const int bx = blockIdx.x * 32;  // n base
  const int by = blockIdx.y * 32;  // k base
  const int x = threadIdx.x & 31, y0 = threadIdx.x >> 5;
#pragma unroll
  for (int i = 0; i < 4; i++) {
    int y = y0 + i * 8;
    t[y][x] = W[(size_t)(by + y) * DD + bx + x];  // W[k][n]
  }
  __syncthreads();
#pragma unroll
  for (int i = 0; i < 4; i++) {
    int y = y0 + i * 8;
    float v = t[x][y];  // WT[n=bx+y][k=by+x]
    __nv_bfloat16 h = __float2bfloat16(v);
    size_t idx = (size_t)(bx + y) * DD + by + x;
    Th[idx] = h;
    Tl[idx] = __float2bfloat16(v - __bfloat162float(h));
  }
}

// ---------------- K1: mma.sync dual GEMM, bf16x3, 8 warps, K=64 stages ------
// grid.x: 0..15 -> W_alpha/sigmoid N-tiles, 16..31 -> W_beta/silu N-tiles
// grid.y: 64 M-tiles. 128x128x64 CTA tile, 8 warps each 32x64, 2 CTAs/SM.
__global__ __launch_bounds__(256, 2) void k_gemm_mma(
    const float* __restrict__ ba, const float* __restrict__ bb) {
  extern __shared__ __align__(1024) char sm[];  // NSTAGE * STAGE_BYTES
  const uint32_t smb = smem_u32(sm);

  const int tid = threadIdx.x;
  const int wid = tid >> 5, lid = tid & 31;
  const int bxv = blockIdx.x;
  const bool isBeta = (bxv >= 16);
  const int n0 = (isBeta ? bxv - 16 : bxv) * Bb_N;
  const int m0 = blockIdx.y * Bb_M;
  const __nv_bfloat16* __restrict__ Bhi = isBeta ? g_WbT_hi : g_WaT_hi;
  const __nv_bfloat16* __restrict__ Blo = isBeta ? g_WbT_lo : g_WaT_lo;
  const float* __restrict__ bias = isBeta ? bb : ba;

  // each stage: A 1024 x 16B chunks + B 1024 x 16B chunks; 256 thr -> 4 each
  auto load_stage = [&](int kc, int buf) {
    const int seg = kc >> 5;            // 32 k-chunks per segment
    const int kk = (kc & 31) * Bb_K;
    const __nv_bfloat16* __restrict__ As =
        ((seg == 1) ? g_gA_lo : g_gA_hi) + (size_t)m0 * DD + kk;
    const __nv_bfloat16* __restrict__ Bs =
        ((seg == 2) ? Blo : Bhi) + (size_t)n0 * DD + kk;
    const uint32_t ab = smb + buf * STAGE_BYTES;
    const uint32_t bbuf = ab + 16384;
#pragma unroll
    for (int i = 0; i < 4; i++) {
      int id = tid + i * 256;           // 0..1023
      int row = id >> 3, cc = id & 7;
      uint32_t soff = (uint32_t)(row * 128 + ((cc ^ (row & 7)) << 4));
      size_t goff = (size_t)row * DD + cc * 8;
      cpa16(ab + soff, As + goff);
      cpa16(bbuf + soff, Bs + goff);
    }
  };

  // warp tiling: wm in {0..3} (32 rows), wn in {0,1} (64 cols)
  const int wm = wid & 3, wn = wid >> 2;
  const int lr = lid & 15, c8 = lid >> 4;

  uint32_t a_off[2], a_swz[2];
#pragma unroll
  for (int mt = 0; mt < 2; mt++) {
    int row = wm * 32 + mt * 16 + lr;
    a_off[mt] = row * 128;
    a_swz[mt] = row & 7;
  }
  uint32_t b_off[4], b_swz[4];
#pragma unroll
  for (int bt = 0; bt < 4; bt++) {
    int row = wn * 64 + bt * 16 + lr;
    b_off[bt] = row * 128;
    b_swz[bt] = row & 7;
  }

  float ac[2][8][4];
#pragma unroll
  for (int i = 0; i < 2; i++)
#pragma unroll
    for (int j = 0; j < 8; j++)
#pragma unroll
      for (int q = 0; q < 4; q++) ac[i][j][q] = 0.f;

  // prefetch first NSTAGE-1 stages
#pragma unroll
  for (int s = 0; s < NSTAGE - 1; s++) { load_stage(s, s); CPA_COMMIT(); }

  int cmp_buf = 0, ld_buf = NSTAGE - 1;
#pragma unroll 1
  for (int kc = 0; kc < KITERS; kc++) {
    CPA_WAIT1();
    __syncthreads();

    const uint32_t abase = smb + cmp_buf * STAGE_BYTES;
    const uint32_t bbase = abase + 16384;

#pragma unroll
    for (int ks = 0; ks < 4; ks++) {
      const uint32_t chunk = (uint32_t)(ks * 2 + c8);
      uint32_t af[2][4], bfr[4][4];
#pragma unroll
      for (int mt = 0; mt < 2; mt++)
        ldmx4(af[mt], abase + a_off[mt] + ((chunk ^ a_swz[mt]) << 4));
#pragma unroll
      for (int bt = 0; bt < 4; bt++)
        ldmx4(bfr[bt], bbase + b_off[bt] + ((chunk ^ b_swz[bt]) << 4));
#pragma unroll
      for (int mt = 0; mt < 2; mt++) {
#pragma unroll
        for (int nt = 0; nt < 8; nt++) {
          const int bt = nt >> 1, sel = nt & 1;
          mma16816(ac[mt][nt], af[mt], bfr[bt][sel], bfr[bt][2 + sel]);
        }
      }
      // overlap: issue next-stage loads after the first ks block
      if (ks == 0) {
        if (kc + NSTAGE - 1 < KITERS) load_stage(kc + NSTAGE - 1, ld_buf);
        CPA_COMMIT();
      }
    }

    cmp_buf = (cmp_buf + 1 == NSTAGE) ? 0 : cmp_buf + 1;
    ld_buf = (ld_buf + 1 == NSTAGE) ? 0 : ld_buf + 1;
  }

  // epilogue: bias + sigmoid/silu, direct global store
  float* __restrict__ dst = isBeta ? g_beta : g_alpha;
  const int g = lid >> 2, tig = lid & 3;
  float bi0[8], bi1[8];
#pragma unroll
  for (int nt = 0; nt < 8; nt++) {
    int col = n0 + wn * 64 + nt * 8 + tig * 2;
    bi0[nt] = __ldg(bias + col);
    bi1[nt] = __ldg(bias + col + 1);
  }
#pragma unroll
  for (int mt = 0; mt < 2; mt++) {
    const int row = m0 + wm * 32 + mt * 16 + g;
#pragma unroll
    for (int nt = 0; nt < 8; nt++) {
      const int col = n0 + wn * 64 + nt * 8 + tig * 2;
      float pr, sg;
      float2 v0, v1;
      pr = ac[mt][nt][0] + bi0[nt];
      sg = 1.0f / (1.0f + __expf(-pr)); v0.x = isBeta ? pr * sg : sg;
      pr = ac[mt][nt][1] + bi1[nt];
      sg = 1.0f / (1.0f + __expf(-pr)); v0.y = isBeta ? pr * sg : sg;
      pr = ac[mt][nt][2] + bi0[nt];
      sg = 1.0f / (1.0f + __expf(-pr)); v1.x = isBeta ? pr * sg : sg;
      pr = ac[mt][nt][3] + bi1[nt];
      sg = 1.0f / (1.0f + __expf(-pr)); v1.y = isBeta ? pr * sg : sg;
      *(float2*)(dst + (size_t)row * DD + col) = v0;
      *(float2*)(dst + (size_t)(row + 8) * DD + col) = v1;
    }
  }
}

// ---------------- x helper ---------------------------------------------------
static __device__ __forceinline__ float x_of(float a, float be, float vv) {
  return vv * be * fast_sqrt(fmaxf(1.0f - a * a, 1e-6f));
}

// ---------------- K3a: per-chunk (A_prod, X_scan), x fused -------------------
__global__ __launch_bounds__(256) void k_scan_chunks(const float* __restrict__ v) {
  const int d = blockIdx.x * 256 + threadIdx.x;
  const int ch = blockIdx.y;
  const int b = blockIdx.z;
  size_t base = ((size_t)(b * SS + ch * CL)) * DD + d;
  float A = 1.f, X = 0.f;
#pragma unroll 8
  for (int t = 0; t < CL; t++) {
    size_t idx = base + (size_t)t * DD;
    float a = g_alpha[idx];
    float x = x_of(a, g_beta[idx], v[idx]);
    X = fmaf(a, X, x);
    A *= a;
  }
  const int o = (b * CH + ch) * DD + d;
  g_Ac[o] = A;
  g_Xc[o] = X;
}

// ---------------- K3b: carry scan across chunks ------------------------------
__global__ __launch_bounds__(256) void k_scan_carry() {
  const int g = blockIdx.x * 256 + threadIdx.x;
  const int b = g / DD;
  const int d = g % DD;
  float H = 0.f;
#pragma unroll 4
  for (int c = 0; c < CH; c++) {
    const int idx = (b * CH + c) * DD + d;
    g_Hin[idx] = H;
    H = fmaf(g_Ac[idx], H, g_Xc[idx]);
  }
}

// ---------------- K3c: final rescan + outputs (o_c handled in K0) -----------
__global__ __launch_bounds__(256) void k_scan_final(
    const float* __restrict__ v, const float* __restrict__ outp,
    const float* __restrict__ gout, const float* __restrict__ gv,
    float* __restrict__ o_v, float* __restrict__ o_out,
    float* __restrict__ o_f) {
  const int d = blockIdx.x * 256 + threadIdx.x;
  const int ch = blockIdx.y;
  const int b = blockIdx.z;
  size_t base = ((size_t)(b * SS + ch * CL)) * DD + d;
  float h = g_Hin[(b * CH + ch) * DD + d];
  const float go = __ldg(&gout[d]);
  const float gvv = __ldg(&gv[d]);
#pragma unroll 4
  for (int t = 0; t < CL; t++) {
    size_t idx = base + (size_t)t * DD;
    float a = g_alpha[idx];
    float vv = v[idx];
    float x = x_of(a, g_beta[idx], vv);
    h = fmaf(a, h, x);
    o_f[idx] = h;
    o_v[idx] = fmaf(h, gvv, vv);
    o_out[idx] = fmaf(h, go, outp[idx]);
  }
}

// ---------------- launch -----------------------------------------------------
extern "C" void kernel_launch(void* const* d_in, const int* in_sizes, int n_in,
                              void* d_out, int out_size) {
  const float* v = (const float*)d_in[0];
  const float* out = (const float*)d_in[1];
  const float* c = (const float*)d_in[2];
  const float* prev = (const float*)d_in[3];
  const float* Wa = (const float*)d_in[4];
  const float* ba = (const float*)d_in[5];
  const float* Wb = (const float*)d_in[6];
  const float* bb = (const float*)d_in[7];
  const float* gout = (const float*)d_in[8];
  const float* gv = (const float*)d_in[9];

  float* o_v = (float*)d_out;
  float* o_out = o_v + MN;
  float* o_c = o_out + MN;
  float* o_f = o_c + MN;

  // K0 (writes o_c = c as fused copy) + W conversion
  k_rmsnorm_split<<<MM, 256>>>(c, prev, o_c);
  {
    dim3 wgrid(DD / 32, DD / 32, 2);
    k_cvt_w<<<wgrid, 256>>>(Wa, Wb);
  }

  // K1: dual GEMM via mma.sync (bf16x3), 8 warps, K=64, 3-stage pipeline
  {
    const int SMEM_BYTES = NSTAGE * STAGE_BYTES;  // 96 KB
    cudaFuncSetAttribute(k_gemm_mma, cudaFuncAttributeMaxDynamicSharedMemorySize,
                         SMEM_BYTES);
    dim3 ggrid(32, 64);
    k_gemm_mma<<<ggrid, 256, SMEM_BYTES>>>(ba, bb);
  }

  // K3: chunked scan (x fused)  [4th launch -> ncu profiles k_scan_chunks]
  dim3 agrid(DD / 256, CH, BB);
  k_scan_chunks<<<agrid, 256>>>(v);
  k_scan_carry<<<(BB * DD) / 256, 256>>>();
  k_scan_final<<<agrid, 256>>>(v, out, gout, gv, o_v, o_out, o_f);
}

// round 15
// speedup vs baseline: 1.0486x; 1.0040x over previous
#include <cuda_runtime.h>
#include <cuda_bf16.h>
#include <math.h>
#include <stdint.h>

// Problem constants
#define BB 2
#define SS 4096
#define DD 2048
#define MM (BB * SS)          // 8192 GEMM rows
#define MN ((size_t)MM * DD)  // elements per tensor
#define CH 64                 // scan chunks
#define CL (SS / CH)          // steps per chunk

#define Bb_M 128
#define Bb_N 128
#define Bb_K 64
#define KITERS 96             // 3 * 2048 / 64  (bf16x3 split folded into K)
#define NSTAGE 3
#define STAGE_BYTES 32768     // 16KB A + 16KB B

// ---------------- scratch (static device memory) ---------------------------
__device__ __align__(256) __nv_bfloat16 g_gA_hi[MN];
__device__ __align__(256) __nv_bfloat16 g_gA_lo[MN];
__device__ __align__(256) __nv_bfloat16 g_WaT_hi[(size_t)DD * DD];
__device__ __align__(256) __nv_bfloat16 g_WaT_lo[(size_t)DD * DD];
__device__ __align__(256) __nv_bfloat16 g_WbT_hi[(size_t)DD * DD];
__device__ __align__(256) __nv_bfloat16 g_WbT_lo[(size_t)DD * DD];
__device__ __align__(256) float g_alpha[MN];  // sigmoid gate
__device__ __align__(256) float g_beta[MN];   // silu gate
__device__ __align__(256) float g_Ac[BB * CH * DD];
__device__ __align__(256) float g_Xc[BB * CH * DD];
__device__ __align__(256) float g_Hin[BB * CH * DD];

// ---------------- PTX helpers ----------------------------------------------
static __device__ __forceinline__ uint32_t smem_u32(const void* p) {
  uint32_t a;
  asm("{ .reg .u64 t; cvta.to.shared.u64 t, %1; cvt.u32.u64 %0, t; }"
      : "=r"(a) : "l"(p));
  return a;
}

static __device__ __forceinline__ void cpa16(uint32_t dst, const void* src) {
  asm volatile("cp.async.cg.shared.global [%0], [%1], 16;" :: "r"(dst), "l"(src));
}
#define CPA_COMMIT() asm volatile("cp.async.commit_group;" ::: "memory")
#define CPA_WAIT1() asm volatile("cp.async.wait_group 1;" ::: "memory")

static __device__ __forceinline__ void ldmx4(uint32_t* r, uint32_t addr) {
  asm volatile(
      "ldmatrix.sync.aligned.m8n8.x4.shared.b16 {%0, %1, %2, %3}, [%4];"
      : "=r"(r[0]), "=r"(r[1]), "=r"(r[2]), "=r"(r[3]) : "r"(addr));
}

static __device__ __forceinline__ void mma16816(
    float* d, const uint32_t* a, uint32_t b0, uint32_t b1) {
  asm volatile(
      "mma.sync.aligned.m16n8k16.row.col.f32.bf16.bf16.f32 "
      "{%0, %1, %2, %3}, {%4, %5, %6, %7}, {%8, %9}, {%0, %1, %2, %3};"
      : "+f"(d[0]), "+f"(d[1]), "+f"(d[2]), "+f"(d[3])
      : "r"(a[0]), "r"(a[1]), "r"(a[2]), "r"(a[3]), "r"(b0), "r"(b1));
}

static __device__ __forceinline__ float fast_sqrt(float z) {
  float r;
  asm("sqrt.approx.f32 %0, %1;" : "=f"(r) : "f"(z));
  return r;
}

// ---------------- K0: fused prep -------------------------------------------
// Blocks [0, MM): gate = rms(c)+rms(prev) -> bf16 hi/lo split, plus o_c = c.
// Blocks [MM, MM+8192): transpose + bf16 split of W_alpha / W_beta.
static __device__ __forceinline__ void split2(float a, float b,
                                              __nv_bfloat162& h, __nv_bfloat162& l) {
  __nv_bfloat16 ha = __float2bfloat16(a), hb = __float2bfloat16(b);
  h = __halves2bfloat162(ha, hb);
  l = __halves2bfloat162(__float2bfloat16(a - __bfloat162float(ha)),
                         __float2bfloat16(b - __bfloat162float(hb)));
}

__global__ __launch_bounds__(256) void k_prep(
    const float* __restrict__ c, const float* __restrict__ p,
    float* __restrict__ o_c,
    const float* __restrict__ Wa, const float* __restrict__ Wb) {
  const int tid = threadIdx.x;

  if (blockIdx.x < MM) {
    // ------- RMS-norm path -------
    const int row = blockIdx.x;
    const float4* c4 = (const float4*)(c + (size_t)row * DD);
    const float4* p4 = (const float4*)(p + (size_t)row * DD);
    float4* oc4 = (float4*)(o_c + (size_t)row * DD);

    float4 cv0 = c4[tid], cv1 = c4[tid + 256];
    float4 pv0 = p4[tid], pv1 = p4[tid + 256];

    // fused o_c = c
    oc4[tid] = cv0;
    oc4[tid + 256] = cv1;

    float sc = cv0.x * cv0.x + cv0.y * cv0.y + cv0.z * cv0.z + cv0.w * cv0.w +
               cv1.x * cv1.x + cv1.y * cv1.y + cv1.z * cv1.z + cv1.w * cv1.w;
    float sp = pv0.x * pv0.x + pv0.y * pv0.y + pv0.z * pv0.z + pv0.w * pv0.w +
               pv1.x * pv1.x + pv1.y * pv1.y + pv1.z * pv1.z + pv1.w * pv1.w;
#pragma unroll
    for (int off = 16; off > 0; off >>= 1) {
      sc += __shfl_xor_sync(0xffffffffu, sc, off);
      sp += __shfl_xor_sync(0xffffffffu, sp, off);
    }
    __shared__ float ssc[8], ssp[8];
    if ((tid & 31) == 0) { ssc[tid >> 5] = sc; ssp[tid >> 5] = sp; }
    __syncthreads();
    float tc = 0.f, tp = 0.f;
#pragma unroll
    for (int i = 0; i < 8; i++) { tc += ssc[i]; tp += ssp[i]; }
    const float rc = rsqrtf(tc * (1.0f / DD) + 1e-6f);
    const float rp = rsqrtf(tp * (1.0f / DD) + 1e-6f);

    float o[8];
    o[0] = cv0.x * rc + pv0.x * rp; o[1] = cv0.y * rc + pv0.y * rp;
    o[2] = cv0.z * rc + pv0.z * rp; o[3] = cv0.w * rc + pv0.w * rp;
    o[4] = cv1.x * rc + pv1.x * rp; o[5] = cv1.y * rc + pv1.y * rp;
    o[6] = cv1.z * rc + pv1.z * rp; o[7] = cv1.w * rc + pv1.w * rp;

    __nv_bfloat162* h2 = (__nv_bfloat162*)(g_gA_hi + (size_t)row * DD);
    __nv_bfloat162* l2 = (__nv_bfloat162*)(g_gA_lo + (size_t)row * DD);
    __nv_bfloat162 h, l;
    split2(o[0], o[1], h, l); h2[2 * tid + 0] = h; l2[2 * tid + 0] = l;
    split2(o[2], o[3], h, l); h2[2 * tid + 1] = h; l2[2 * tid + 1] = l;
    split2(o[4], o[5], h, l); h2[2 * (tid + 256) + 0] = h; l2[2 * (tid + 256) + 0] = l;
    split2(o[6], o[7], h, l); h2[2 * (tid + 256) + 1] = h; l2[2 * (tid + 256) + 1] = l;
  } else {
    // ------- W transpose + split path -------
    __shared__ float t[32][33];
    const int idx = blockIdx.x - MM;       // 0..8191
    const int mat = idx >> 12;             // 0 or 1 (4096 blocks per matrix)
    const int rem = idx & 4095;
    const int bx = (rem & 63) * 32;        // n base
    const int by = (rem >> 6) * 32;        // k base
    const float* __restrict__ W = mat ? Wb : Wa;
    __nv_bfloat16* __restrict__ Th = mat ? g_WbT_hi : g_WaT_hi;
    __nv_bfloat16* __restrict__ Tl = mat ? g_WbT_lo : g_WaT_lo;
    const int x = tid & 31, y0 = tid >> 5;
#pragma unroll
    for (int i = 0; i < 4; i++) {
      int y = y0 + i * 8;
      t[y][x] = W[(size_t)(by + y) * DD + bx + x];  // W[k][n]
    }
    __syncthreads();
#pragma unroll
    for (int i = 0; i < 4; i++) {
      int y = y0 + i * 8;
      float v = t[x][y];  // WT[n=bx+y][k=by+x]
      __nv_bfloat16 h = __float2bfloat16(v);
      size_t widx = (size_t)(bx + y) * DD + by + x;
      Th[widx] = h;
      Tl[widx] = __float2bfloat16(v - __bfloat162float(h));
    }
  }
}

// ---------------- K1: mma.sync dual GEMM, bf16x3, 8 warps, K=64 stages ------
// grid.x: 0..15 -> W_alpha/sigmoid N-tiles, 16..31 -> W_beta/silu N-tiles
// grid.y: 64 M-tiles. 128x128x64 CTA tile, 8 warps each 32x64, 2 CTAs/SM.
__global__ __launch_bounds__(256, 2) void k_gemm_mma(
    const float* __restrict__ ba, const float* __restrict__ bb) {
  extern __shared__ __align__(1024) char sm[];  // NSTAGE * STAGE_BYTES
  const uint32_t smb = smem_u32(sm);

  const int tid = threadIdx.x;
  const int wid = tid >> 5, lid = tid & 31;
  const int bxv = blockIdx.x;
  const bool isBeta = (bxv >= 16);
  const int n0 = (isBeta ? bxv - 16 : bxv) * Bb_N;
  const int m0 = blockIdx.y * Bb_M;
  const __nv_bfloat16* __restrict__ Bhi = isBeta ? g_WbT_hi : g_WaT_hi;
  const __nv_bfloat16* __restrict__ Blo = isBeta ? g_WbT_lo : g_WaT_lo;
  const float* __restrict__ bias = isBeta ? bb : ba;

  // each stage: A 1024 x 16B chunks + B 1024 x 16B chunks; 256 thr -> 4 each
  auto load_stage = [&](int kc, int buf) {
    const int seg = kc >> 5;            // 32 k-chunks per segment
    const int kk = (kc & 31) * Bb_K;
    const __nv_bfloat16* __restrict__ As =
        ((seg == 1) ? g_gA_lo : g_gA_hi) + (size_t)m0 * DD + kk;
    const __nv_bfloat16* __restrict__ Bs =
        ((seg == 2) ? Blo : Bhi) + (size_t)n0 * DD + kk;
    const uint32_t ab = smb + buf * STAGE_BYTES;
    const uint32_t bbuf = ab + 16384;
#pragma unroll
    for (int i = 0; i < 4; i++) {
      int id = tid + i * 256;           // 0..1023
      int row = id >> 3, cc = id & 7;
      uint32_t soff = (uint32_t)(row * 128 + ((cc ^ (row & 7)) << 4));
      size_t goff = (size_t)row * DD + cc * 8;
      cpa16(ab + soff, As + goff);
      cpa16(bbuf + soff, Bs + goff);
    }
  };

  // warp tiling: wm in {0..3} (32 rows), wn in {0,1} (64 cols)
  const int wm = wid & 3, wn = wid >> 2;
  const int lr = lid & 15, c8 = lid >> 4;

  uint32_t a_off[2], a_swz[2];
#pragma unroll
  for (int mt = 0; mt < 2; mt++) {
    int row = wm * 32 + mt * 16 + lr;
    a_off[mt] = row * 128;
    a_swz[mt] = row & 7;
  }
  uint32_t b_off[4], b_swz[4];
#pragma unroll
  for (int bt = 0; bt < 4; bt++) {
    int row = wn * 64 + bt * 16 + lr;
    b_off[bt] = row * 128;
    b_swz[bt] = row & 7;
  }

  float ac[2][8][4];
#pragma unroll
  for (int i = 0; i < 2; i++)
#pragma unroll
    for (int j = 0; j < 8; j++)
#pragma unroll
      for (int q = 0; q < 4; q++) ac[i][j][q] = 0.f;

  // prefetch first NSTAGE-1 stages
#pragma unroll
  for (int s = 0; s < NSTAGE - 1; s++) { load_stage(s, s); CPA_COMMIT(); }

  int cmp_buf = 0, ld_buf = NSTAGE - 1;
#pragma unroll 1
  for (int kc = 0; kc < KITERS; kc++) {
    CPA_WAIT1();
    __syncthreads();

    const uint32_t abase = smb + cmp_buf * STAGE_BYTES;
    const uint32_t bbase = abase + 16384;

#pragma unroll
    for (int ks = 0; ks < 4; ks++) {
      const uint32_t chunk = (uint32_t)(ks * 2 + c8);
      uint32_t af[2][4], bfr[4][4];
#pragma unroll
      for (int mt = 0; mt < 2; mt++)
        ldmx4(af[mt], abase + a_off[mt] + ((chunk ^ a_swz[mt]) << 4));
#pragma unroll
      for (int bt = 0; bt < 4; bt++)
        ldmx4(bfr[bt], bbase + b_off[bt] + ((chunk ^ b_swz[bt]) << 4));
#pragma unroll
      for (int mt = 0; mt < 2; mt++) {
#pragma unroll
        for (int nt = 0; nt < 8; nt++) {
          const int bt = nt >> 1, sel = nt & 1;
          mma16816(ac[mt][nt], af[mt], bfr[bt][sel], bfr[bt][2 + sel]);
        }
      }
      // overlap: issue next-stage loads after the first ks block
      if (ks == 0) {
        if (kc + NSTAGE - 1 < KITERS) load_stage(kc + NSTAGE - 1, ld_buf);
        CPA_COMMIT();
      }
    }

    cmp_buf = (cmp_buf + 1 == NSTAGE) ? 0 : cmp_buf + 1;
    ld_buf = (ld_buf + 1 == NSTAGE) ? 0 : ld_buf + 1;
  }

  // epilogue: bias + sigmoid/silu, direct global store
  float* __restrict__ dst = isBeta ? g_beta : g_alpha;
  const int g = lid >> 2, tig = lid & 3;
  float bi0[8], bi1[8];
#pragma unroll
  for (int nt = 0; nt < 8; nt++) {
    int col = n0 + wn * 64 + nt * 8 + tig * 2;
    bi0[nt] = __ldg(bias + col);
    bi1[nt] = __ldg(bias + col + 1);
  }
#pragma unroll
  for (int mt = 0; mt < 2; mt++) {
    const int row = m0 + wm * 32 + mt * 16 + g;
#pragma unroll
    for (int nt = 0; nt < 8; nt++) {
      const int col = n0 + wn * 64 + nt * 8 + tig * 2;
      float pr, sg;
      float2 v0, v1;
      pr = ac[mt][nt][0] + bi0[nt];
      sg = 1.0f / (1.0f + __expf(-pr)); v0.x = isBeta ? pr * sg : sg;
      pr = ac[mt][nt][1] + bi1[nt];
      sg = 1.0f / (1.0f + __expf(-pr)); v0.y = isBeta ? pr * sg : sg;
      pr = ac[mt][nt][2] + bi0[nt];
      sg = 1.0f / (1.0f + __expf(-pr)); v1.x = isBeta ? pr * sg : sg;
      pr = ac[mt][nt][3] + bi1[nt];
      sg = 1.0f / (1.0f + __expf(-pr)); v1.y = isBeta ? pr * sg : sg;
      *(float2*)(dst + (size_t)row * DD + col) = v0;
      *(float2*)(dst + (size_t)(row + 8) * DD + col) = v1;
    }
  }
}

// ---------------- x helper ---------------------------------------------------
static __device__ __forceinline__ float x_of(float a, float be, float vv) {
  return vv * be * fast_sqrt(fmaxf(1.0f - a * a, 1e-6f));
}

// ---------------- K3a: per-chunk (A_prod, X_scan), x fused -------------------
__global__ __launch_bounds__(256) void k_scan_chunks(const float* __restrict__ v) {
  const int d = blockIdx.x * 256 + threadIdx.x;
  const int ch = blockIdx.y;
  const int b = blockIdx.z;
  size_t base = ((size_t)(b * SS + ch * CL)) * DD + d;
  float A = 1.f, X = 0.f;
#pragma unroll 8
  for (int t = 0; t < CL; t++) {
    size_t idx = base + (size_t)t * DD;
    float a = g_alpha[idx];
    float x = x_of(a, g_beta[idx], v[idx]);
    X = fmaf(a, X, x);
    A *= a;
  }
  const int o = (b * CH + ch) * DD + d;
  g_Ac[o] = A;
  g_Xc[o] = X;
}

// ---------------- K3b: carry scan across chunks ------------------------------
__global__ __launch_bounds__(256) void k_scan_carry() {
  const int g = blockIdx.x * 256 + threadIdx.x;
  const int b = g / DD;
  const int d = g % DD;
  float H = 0.f;
#pragma unroll 4
  for (int c = 0; c < CH; c++) {
    const int idx = (b * CH + c) * DD + d;
    g_Hin[idx] = H;
    H = fmaf(g_Ac[idx], H, g_Xc[idx]);
  }
}

// ---------------- K3c: final rescan + outputs (o_c handled in K0) -----------
__global__ __launch_bounds__(256) void k_scan_final(
    const float* __restrict__ v, const float* __restrict__ outp,
    const float* __restrict__ gout, const float* __restrict__ gv,
    float* __restrict__ o_v, float* __restrict__ o_out,
    float* __restrict__ o_f) {
  const int d = blockIdx.x * 256 + threadIdx.x;
  const int ch = blockIdx.y;
  const int b = blockIdx.z;
  size_t base = ((size_t)(b * SS + ch * CL)) * DD + d;
  float h = g_Hin[(b * CH + ch) * DD + d];
  const float go = __ldg(&gout[d]);
  const float gvv = __ldg(&gv[d]);
#pragma unroll 4
  for (int t = 0; t < CL; t++) {
    size_t idx = base + (size_t)t * DD;
    float a = g_alpha[idx];
    float vv = v[idx];
    float x = x_of(a, g_beta[idx], vv);
    h = fmaf(a, h, x);
    o_f[idx] = h;
    o_v[idx] = fmaf(h, gvv, vv);
    o_out[idx] = fmaf(h, go, outp[idx]);
  }
}

// ---------------- launch -----------------------------------------------------
extern "C" void kernel_launch(void* const* d_in, const int* in_sizes, int n_in,
                              void* d_out, int out_size) {
  const float* v = (const float*)d_in[0];
  const float* out = (const float*)d_in[1];
  const float* c = (const float*)d_in[2];
  const float* prev = (const float*)d_in[3];
  const float* Wa = (const float*)d_in[4];
  const float* ba = (const float*)d_in[5];
  const float* Wb = (const float*)d_in[6];
  const float* bb = (const float*)d_in[7];
  const float* gout = (const float*)d_in[8];
  const float* gv = (const float*)d_in[9];

  float* o_v = (float*)d_out;
  float* o_out = o_v + MN;
  float* o_c = o_out + MN;
  float* o_f = o_c + MN;

  // K0: fused rms-norm + o_c copy + W transpose/split (single launch)
  k_prep<<<MM + 8192, 256>>>(c, prev, o_c, Wa, Wb);

  // K1: dual GEMM via mma.sync (bf16x3), 8 warps, K=64, 3-stage pipeline
  {
    const int SMEM_BYTES = NSTAGE * STAGE_BYTES;  // 96 KB
    cudaFuncSetAttribute(k_gemm_mma, cudaFuncAttributeMaxDynamicSharedMemorySize,
                         SMEM_BYTES);
    dim3 ggrid(32, 64);
    k_gemm_mma<<<ggrid, 256, SMEM_BYTES>>>(ba, bb);
  }

  // K3: chunked scan (x fused)
  dim3 agrid(DD / 256, CH, BB);
  k_scan_chunks<<<agrid, 256>>>(v);
  k_scan_carry<<<(BB * DD) / 256, 256>>>();
  k_scan_final<<<agrid, 256>>>(v, out, gout, gv, o_v, o_out, o_f);
}

// round 16
// speedup vs baseline: 1.0605x; 1.0114x over previous
#include <cuda_runtime.h>
#include <cuda_bf16.h>
#include <math.h>
#include <stdint.h>

// Problem constants
#define BB 2
#define SS 4096
#define DD 2048
#define MM (BB * SS)          // 8192 GEMM rows
#define MN ((size_t)MM * DD)  // elements per tensor
#define CH 64                 // scan chunks
#define CL (SS / CH)          // steps per chunk

#define Bb_M 128
#define Bb_N 128
#define Bb_K 64
#define KITERS 96             // 3 * 2048 / 64  (bf16x3 split folded into K)
#define NSTAGE 3
#define STAGE_BYTES 32768     // 16KB A + 16KB B

// ---------------- scratch (static device memory) ---------------------------
__device__ __align__(256) __nv_bfloat16 g_gA_hi[MN];
__device__ __align__(256) __nv_bfloat16 g_gA_lo[MN];
__device__ __align__(256) __nv_bfloat16 g_WaT_hi[(size_t)DD * DD];
__device__ __align__(256) __nv_bfloat16 g_WaT_lo[(size_t)DD * DD];
__device__ __align__(256) __nv_bfloat16 g_WbT_hi[(size_t)DD * DD];
__device__ __align__(256) __nv_bfloat16 g_WbT_lo[(size_t)DD * DD];
__device__ __align__(256) float g_alpha[MN];  // sigmoid gate
__device__ __align__(256) float g_beta[MN];   // silu gate
__device__ __align__(256) float g_Ac[BB * CH * DD];
__device__ __align__(256) float g_Xc[BB * CH * DD];
__device__ __align__(256) float g_Hin[BB * CH * DD];

// ---------------- PTX helpers ----------------------------------------------
static __device__ __forceinline__ uint32_t smem_u32(const void* p) {
  uint32_t a;
  asm("{ .reg .u64 t; cvta.to.shared.u64 t, %1; cvt.u32.u64 %0, t; }"
      : "=r"(a) : "l"(p));
  return a;
}

static __device__ __forceinline__ void cpa16(uint32_t dst, const void* src) {
  asm volatile("cp.async.cg.shared.global [%0], [%1], 16;" :: "r"(dst), "l"(src));
}
#define CPA_COMMIT() asm volatile("cp.async.commit_group;" ::: "memory")
#define CPA_WAIT1() asm volatile("cp.async.wait_group 1;" ::: "memory")

static __device__ __forceinline__ void ldmx4(uint32_t* r, uint32_t addr) {
  asm volatile(
      "ldmatrix.sync.aligned.m8n8.x4.shared.b16 {%0, %1, %2, %3}, [%4];"
      : "=r"(r[0]), "=r"(r[1]), "=r"(r[2]), "=r"(r[3]) : "r"(addr));
}

static __device__ __forceinline__ void mma16816(
    float* d, const uint32_t* a, uint32_t b0, uint32_t b1) {
  asm volatile(
      "mma.sync.aligned.m16n8k16.row.col.f32.bf16.bf16.f32 "
      "{%0, %1, %2, %3}, {%4, %5, %6, %7}, {%8, %9}, {%0, %1, %2, %3};"
      : "+f"(d[0]), "+f"(d[1]), "+f"(d[2]), "+f"(d[3])
      : "r"(a[0]), "r"(a[1]), "r"(a[2]), "r"(a[3]), "r"(b0), "r"(b1));
}

static __device__ __forceinline__ float fast_sqrt(float z) {
  float r;
  asm("sqrt.approx.f32 %0, %1;" : "=f"(r) : "f"(z));
  return r;
}

// ---------------- K0: fused prep -------------------------------------------
// Blocks [0, MM): gate = rms(c)+rms(prev) -> bf16 hi/lo split, plus o_c = c.
// Blocks [MM, MM+8192): transpose + bf16 split of W_alpha / W_beta.
static __device__ __forceinline__ void split2(float a, float b,
                                              __nv_bfloat162& h, __nv_bfloat162& l) {
  __nv_bfloat16 ha = __float2bfloat16(a), hb = __float2bfloat16(b);
  h = __halves2bfloat162(ha, hb);
  l = __halves2bfloat162(__float2bfloat16(a - __bfloat162float(ha)),
                         __float2bfloat16(b - __bfloat162float(hb)));
}

__global__ __launch_bounds__(256) void k_prep(
    const float* __restrict__ c, const float* __restrict__ p,
    float* __restrict__ o_c,
    const float* __restrict__ Wa, const float* __restrict__ Wb) {
  const int tid = threadIdx.x;

  if (blockIdx.x < MM) {
    // ------- RMS-norm path -------
    const int row = blockIdx.x;
    const float4* c4 = (const float4*)(c + (size_t)row * DD);
    const float4* p4 = (const float4*)(p + (size_t)row * DD);
    float4* oc4 = (float4*)(o_c + (size_t)row * DD);

    float4 cv0 = c4[tid], cv1 = c4[tid + 256];
    float4 pv0 = p4[tid], pv1 = p4[tid + 256];

    // fused o_c = c
    oc4[tid] = cv0;
    oc4[tid + 256] = cv1;

    float sc = cv0.x * cv0.x + cv0.y * cv0.y + cv0.z * cv0.z + cv0.w * cv0.w +
               cv1.x * cv1.x + cv1.y * cv1.y + cv1.z * cv1.z + cv1.w * cv1.w;
    float sp = pv0.x * pv0.x + pv0.y * pv0.y + pv0.z * pv0.z + pv0.w * pv0.w +
               pv1.x * pv1.x + pv1.y * pv1.y + pv1.z * pv1.z + pv1.w * pv1.w;
#pragma unroll
    for (int off = 16; off > 0; off >>= 1) {
      sc += __shfl_xor_sync(0xffffffffu, sc, off);
      sp += __shfl_xor_sync(0xffffffffu, sp, off);
    }
    __shared__ float ssc[8], ssp[8];
    if ((tid & 31) == 0) { ssc[tid >> 5] = sc; ssp[tid >> 5] = sp; }
    __syncthreads();
    float tc = 0.f, tp = 0.f;
#pragma unroll
    for (int i = 0; i < 8; i++) { tc += ssc[i]; tp += ssp[i]; }
    const float rc = rsqrtf(tc * (1.0f / DD) + 1e-6f);
    const float rp = rsqrtf(tp * (1.0f / DD) + 1e-6f);

    float o[8];
    o[0] = cv0.x * rc + pv0.x * rp; o[1] = cv0.y * rc + pv0.y * rp;
    o[2] = cv0.z * rc + pv0.z * rp; o[3] = cv0.w * rc + pv0.w * rp;
    o[4] = cv1.x * rc + pv1.x * rp; o[5] = cv1.y * rc + pv1.y * rp;
    o[6] = cv1.z * rc + pv1.z * rp; o[7] = cv1.w * rc + pv1.w * rp;

    __nv_bfloat162* h2 = (__nv_bfloat162*)(g_gA_hi + (size_t)row * DD);
    __nv_bfloat162* l2 = (__nv_bfloat162*)(g_gA_lo + (size_t)row * DD);
    __nv_bfloat162 h, l;
    split2(o[0], o[1], h, l); h2[2 * tid + 0] = h; l2[2 * tid + 0] = l;
    split2(o[2], o[3], h, l); h2[2 * tid + 1] = h; l2[2 * tid + 1] = l;
    split2(o[4], o[5], h, l); h2[2 * (tid + 256) + 0] = h; l2[2 * (tid + 256) + 0] = l;
    split2(o[6], o[7], h, l); h2[2 * (tid + 256) + 1] = h; l2[2 * (tid + 256) + 1] = l;
  } else {
    // ------- W transpose + split path -------
    __shared__ float t[32][33];
    const int idx = blockIdx.x - MM;       // 0..8191
    const int mat = idx >> 12;             // 0 or 1 (4096 blocks per matrix)
    const int rem = idx & 4095;
    const int bx = (rem & 63) * 32;        // n base
    const int by = (rem >> 6) * 32;        // k base
    const float* __restrict__ W = mat ? Wb : Wa;
    __nv_bfloat16* __restrict__ Th = mat ? g_WbT_hi : g_WaT_hi;
    __nv_bfloat16* __restrict__ Tl = mat ? g_WbT_lo : g_WaT_lo;
    const int x = tid & 31, y0 = tid >> 5;
#pragma unroll
    for (int i = 0; i < 4; i++) {
      int y = y0 + i * 8;
      t[y][x] = W[(size_t)(by + y) * DD + bx + x];  // W[k][n]
    }
    __syncthreads();
#pragma unroll
    for (int i = 0; i < 4; i++) {
      int y = y0 + i * 8;
      float v = t[x][y];  // WT[n=bx+y][k=by+x]
      __nv_bfloat16 h = __float2bfloat16(v);
      size_t widx = (size_t)(bx + y) * DD + by + x;
      Th[widx] = h;
      Tl[widx] = __float2bfloat16(v - __bfloat162float(h));
    }
  }
}

// ---------------- K1: mma.sync dual GEMM, bf16x3, 8 warps, K=64 stages ------
// grid.x: 0..15 -> W_alpha/sigmoid N-tiles, 16..31 -> W_beta/silu N-tiles
// grid.y: 64 M-tiles. 128x128x64 CTA tile, 8 warps each 32x64, 2 CTAs/SM.
__global__ __launch_bounds__(256, 2) void k_gemm_mma(
    const float* __restrict__ ba, const float* __restrict__ bb) {
  extern __shared__ __align__(1024) char sm[];  // NSTAGE * STAGE_BYTES
  const uint32_t smb = smem_u32(sm);

  const int tid = threadIdx.x;
  const int wid = tid >> 5, lid = tid & 31;
  const int bxv = blockIdx.x;
  const bool isBeta = (bxv >= 16);
  const int n0 = (isBeta ? bxv - 16 : bxv) * Bb_N;
  const int m0 = blockIdx.y * Bb_M;
  const __nv_bfloat16* __restrict__ Bhi = isBeta ? g_WbT_hi : g_WaT_hi;
  const __nv_bfloat16* __restrict__ Blo = isBeta ? g_WbT_lo : g_WaT_lo;
  const float* __restrict__ bias = isBeta ? bb : ba;

  // each stage: A 1024 x 16B chunks + B 1024 x 16B chunks; 256 thr -> 4 each
  auto load_stage = [&](int kc, int buf) {
    const int seg = kc >> 5;            // 32 k-chunks per segment
    const int kk = (kc & 31) * Bb_K;
    const __nv_bfloat16* __restrict__ As =
        ((seg == 1) ? g_gA_lo : g_gA_hi) + (size_t)m0 * DD + kk;
    const __nv_bfloat16* __restrict__ Bs =
        ((seg == 2) ? Blo : Bhi) + (size_t)n0 * DD + kk;
    const uint32_t ab = smb + buf * STAGE_BYTES;
    const uint32_t bbuf = ab + 16384;
#pragma unroll
    for (int i = 0; i < 4; i++) {
      int id = tid + i * 256;           // 0..1023
      int row = id >> 3, cc = id & 7;
      uint32_t soff = (uint32_t)(row * 128 + ((cc ^ (row & 7)) << 4));
      size_t goff = (size_t)row * DD + cc * 8;
      cpa16(ab + soff, As + goff);
      cpa16(bbuf + soff, Bs + goff);
    }
  };

  // warp tiling: wm in {0..3} (32 rows), wn in {0,1} (64 cols)
  const int wm = wid & 3, wn = wid >> 2;
  const int lr = lid & 15, c8 = lid >> 4;

  uint32_t a_off[2], a_swz[2];
#pragma unroll
  for (int mt = 0; mt < 2; mt++) {
    int row = wm * 32 + mt * 16 + lr;
    a_off[mt] = row * 128;
    a_swz[mt] = row & 7;
  }
  uint32_t b_off[4], b_swz[4];
#pragma unroll
  for (int bt = 0; bt < 4; bt++) {
    int row = wn * 64 + bt * 16 + lr;
    b_off[bt] = row * 128;
    b_swz[bt] = row & 7;
  }

  float ac[2][8][4];
#pragma unroll
  for (int i = 0; i < 2; i++)
#pragma unroll
    for (int j = 0; j < 8; j++)
#pragma unroll
      for (int q = 0; q < 4; q++) ac[i][j][q] = 0.f;

  // prefetch first NSTAGE-1 stages
#pragma unroll
  for (int s = 0; s < NSTAGE - 1; s++) { load_stage(s, s); CPA_COMMIT(); }

  int cmp_buf = 0, ld_buf = NSTAGE - 1;
#pragma unroll 1
  for (int kc = 0; kc < KITERS; kc++) {
    CPA_WAIT1();
    __syncthreads();

    const uint32_t abase = smb + cmp_buf * STAGE_BYTES;
    const uint32_t bbase = abase + 16384;

#pragma unroll
    for (int ks = 0; ks < 4; ks++) {
      const uint32_t chunk = (uint32_t)(ks * 2 + c8);
      uint32_t af[2][4], bfr[4][4];
#pragma unroll
      for (int mt = 0; mt < 2; mt++)
        ldmx4(af[mt], abase + a_off[mt] + ((chunk ^ a_swz[mt]) << 4));
#pragma unroll
      for (int bt = 0; bt < 4; bt++)
        ldmx4(bfr[bt], bbase + b_off[bt] + ((chunk ^ b_swz[bt]) << 4));
#pragma unroll
      for (int mt = 0; mt < 2; mt++) {
#pragma unroll
        for (int nt = 0; nt < 8; nt++) {
          const int bt = nt >> 1, sel = nt & 1;
          mma16816(ac[mt][nt], af[mt], bfr[bt][sel], bfr[bt][2 + sel]);
        }
      }
      // overlap: issue next-stage loads after the first ks block
      if (ks == 0) {
        if (kc + NSTAGE - 1 < KITERS) load_stage(kc + NSTAGE - 1, ld_buf);
        CPA_COMMIT();
      }
    }

    cmp_buf = (cmp_buf + 1 == NSTAGE) ? 0 : cmp_buf + 1;
    ld_buf = (ld_buf + 1 == NSTAGE) ? 0 : ld_buf + 1;
  }

  // epilogue: bias + sigmoid/silu, direct global store
  float* __restrict__ dst = isBeta ? g_beta : g_alpha;
  const int g = lid >> 2, tig = lid & 3;
  float bi0[8], bi1[8];
#pragma unroll
  for (int nt = 0; nt < 8; nt++) {
    int col = n0 + wn * 64 + nt * 8 + tig * 2;
    bi0[nt] = __ldg(bias + col);
    bi1[nt] = __ldg(bias + col + 1);
  }
#pragma unroll
  for (int mt = 0; mt < 2; mt++) {
    const int row = m0 + wm * 32 + mt * 16 + g;
#pragma unroll
    for (int nt = 0; nt < 8; nt++) {
      const int col = n0 + wn * 64 + nt * 8 + tig * 2;
      float pr, sg;
      float2 v0, v1;
      pr = ac[mt][nt][0] + bi0[nt];
      sg = 1.0f / (1.0f + __expf(-pr)); v0.x = isBeta ? pr * sg : sg;
      pr = ac[mt][nt][1] + bi1[nt];
      sg = 1.0f / (1.0f + __expf(-pr)); v0.y = isBeta ? pr * sg : sg;
      pr = ac[mt][nt][2] + bi0[nt];
      sg = 1.0f / (1.0f + __expf(-pr)); v1.x = isBeta ? pr * sg : sg;
      pr = ac[mt][nt][3] + bi1[nt];
      sg = 1.0f / (1.0f + __expf(-pr)); v1.y = isBeta ? pr * sg : sg;
      *(float2*)(dst + (size_t)row * DD + col) = v0;
      *(float2*)(dst + (size_t)(row + 8) * DD + col) = v1;
    }
  }
}

// ---------------- x helper ---------------------------------------------------
static __device__ __forceinline__ float x_of(float a, float be, float vv) {
  return vv * be * fast_sqrt(fmaxf(1.0f - a * a, 1e-6f));
}

// ---------------- K3a: per-chunk (A_prod, X_scan), x fused -------------------
__global__ __launch_bounds__(256) void k_scan_chunks(const float* __restrict__ v) {
  const int d = blockIdx.x * 256 + threadIdx.x;
  const int ch = blockIdx.y;
  const int b = blockIdx.z;
  size_t base = ((size_t)(b * SS + ch * CL)) * DD + d;
  float A = 1.f, X = 0.f;
#pragma unroll 8
  for (int t = 0; t < CL; t++) {
    size_t idx = base + (size_t)t * DD;
    float a = g_alpha[idx];
    float x = x_of(a, g_beta[idx], v[idx]);
    X = fmaf(a, X, x);
    A *= a;
  }
  const int o = (b * CH + ch) * DD + d;
  g_Ac[o] = A;
  g_Xc[o] = X;
}

// ---------------- K3b: carry scan, software-prefetch pipeline ---------------
// 4096 lanes (b,d); each scans CH=64 chunks. Loads for batch c+4 are issued
// before consuming batch c, so only the FMA chain is serial.
__global__ __launch_bounds__(64) void k_scan_carry() {
  const int g = blockIdx.x * 64 + threadIdx.x;  // 0..4095
  const int b = g >> 11;                        // g / DD
  const int d = g & (DD - 1);
  const int base = b * CH * DD + d;

  float A[4], X[4];
#pragma unroll
  for (int i = 0; i < 4; i++) {
    A[i] = g_Ac[base + i * DD];
    X[i] = g_Xc[base + i * DD];
  }

  float H = 0.f;
#pragma unroll
  for (int c = 0; c < CH; c += 4) {
    float An[4], Xn[4];
    if (c + 4 < CH) {
#pragma unroll
      for (int i = 0; i < 4; i++) {
        An[i] = g_Ac[base + (c + 4 + i) * DD];
        Xn[i] = g_Xc[base + (c + 4 + i) * DD];
      }
    } else {
#pragma unroll
      for (int i = 0; i < 4; i++) { An[i] = 0.f; Xn[i] = 0.f; }
    }
#pragma unroll
    for (int i = 0; i < 4; i++) {
      g_Hin[base + (c + i) * DD] = H;
      H = fmaf(A[i], H, X[i]);
    }
#pragma unroll
    for (int i = 0; i < 4; i++) { A[i] = An[i]; X[i] = Xn[i]; }
  }
}

// ---------------- K3c: final rescan + outputs (o_c handled in K0) -----------
__global__ __launch_bounds__(256) void k_scan_final(
    const float* __restrict__ v, const float* __restrict__ outp,
    const float* __restrict__ gout, const float* __restrict__ gv,
    float* __restrict__ o_v, float* __restrict__ o_out,
    float* __restrict__ o_f) {
  const int d = blockIdx.x * 256 + threadIdx.x;
  const int ch = blockIdx.y;
  const int b = blockIdx.z;
  size_t base = ((size_t)(b * SS + ch * CL)) * DD + d;
  float h = g_Hin[(b * CH + ch) * DD + d];
  const float go = __ldg(&gout[d]);
  const float gvv = __ldg(&gv[d]);
#pragma unroll 4
  for (int t = 0; t < CL; t++) {
    size_t idx = base + (size_t)t * DD;
    float a = g_alpha[idx];
    float vv = v[idx];
    float x = x_of(a, g_beta[idx], vv);
    h = fmaf(a, h, x);
    o_f[idx] = h;
    o_v[idx] = fmaf(h, gvv, vv);
    o_out[idx] = fmaf(h, go, outp[idx]);
  }
}

// ---------------- launch -----------------------------------------------------
extern "C" void kernel_launch(void* const* d_in, const int* in_sizes, int n_in,
                              void* d_out, int out_size) {
  const float* v = (const float*)d_in[0];
  const float* out = (const float*)d_in[1];
  const float* c = (const float*)d_in[2];
  const float* prev = (const float*)d_in[3];
  const float* Wa = (const float*)d_in[4];
  const float* ba = (const float*)d_in[5];
  const float* Wb = (const float*)d_in[6];
  const float* bb = (const float*)d_in[7];
  const float* gout = (const float*)d_in[8];
  const float* gv = (const float*)d_in[9];

  float* o_v = (float*)d_out;
  float* o_out = o_v + MN;
  float* o_c = o_out + MN;
  float* o_f = o_c + MN;

  // K0: fused rms-norm + o_c copy + W transpose/split (single launch)
  k_prep<<<MM + 8192, 256>>>(c, prev, o_c, Wa, Wb);

  // K1: dual GEMM via mma.sync (bf16x3), 8 warps, K=64, 3-stage pipeline
  {
    const int SMEM_BYTES = NSTAGE * STAGE_BYTES;  // 96 KB
    cudaFuncSetAttribute(k_gemm_mma, cudaFuncAttributeMaxDynamicSharedMemorySize,
                         SMEM_BYTES);
    dim3 ggrid(32, 64);
    k_gemm_mma<<<ggrid, 256, SMEM_BYTES>>>(ba, bb);
  }

  // K3: chunked scan (x fused)
  dim3 agrid(DD / 256, CH, BB);
  k_scan_chunks<<<agrid, 256>>>(v);
  k_scan_carry<<<(BB * DD) / 64, 64>>>();
  k_scan_final<<<agrid, 256>>>(v, out, gout, gv, o_v, o_out, o_f);
}